// round 17
// baseline (speedup 1.0000x reference)
#include <cuda_runtime.h>
#include <stdint.h>

#define B_   128
#define S_   512
#define T_   24
#define D_   256
#define H_   4
#define HD_  64
#define N_   (B_*S_)            // 65536
#define NT_  (N_*T_)            // 1572864
#define KOSC (-500.0f)
#define NOISE_TH 0.0241f

typedef unsigned long long ull;
typedef unsigned short ushortx;

// Precomputed tables (device globals: no allocation allowed)
__device__ __align__(16) float d_k [H_*T_*HD_];
__device__ __align__(16) float d_v [H_*T_*HD_];
__device__ __align__(16) float d_qt[H_*T_*HD_];
__device__ __align__(16) float d_qu[H_*B_*HD_];
__device__ __align__(16) float d_st[H_*T_*T_];
__device__ __align__(16) float d_su[H_*B_*T_];
__device__ __align__(16) ull   d_W2[48*256];   // (W[2kp][c], W[2kp+1][c]) pairs
__device__ __align__(16) float d_Wh[96*24];    // head cols [kt][c]
__device__ __align__(16) float d_bias[280];
__device__ __align__(16) float d_P [N_*96];    // probs staging (25 MB)
__device__ unsigned d_ku[2];
__device__ unsigned d_kv[2];

// ---------- packed f32x2 helpers ----------
__device__ __forceinline__ void ffma2(ull &d, ull a, ull b) {
    asm("fma.rn.f32x2 %0, %1, %2, %0;" : "+l"(d) : "l"(a), "l"(b));
}
__device__ __forceinline__ ull dup2(float v) {
    unsigned b = __float_as_uint(v);
    ull r; asm("mov.b64 %0, {%1, %1};" : "=l"(r) : "r"(b)); return r;
}

// ---------- JAX threefry2x32 (exact) ----------
__device__ __forceinline__ void tf2x32(unsigned k0, unsigned k1,
                                       unsigned x0, unsigned x1,
                                       unsigned &o0, unsigned &o1) {
    unsigned k2 = k0 ^ k1 ^ 0x1BD11BDAu;
    x0 += k0; x1 += k1;
#define RD_(r) { x0 += x1; x1 = (x1 << (r)) | (x1 >> (32 - (r))); x1 ^= x0; }
    RD_(13) RD_(15) RD_(26) RD_(6)   x0 += k1; x1 += k2 + 1u;
    RD_(17) RD_(29) RD_(16) RD_(24)  x0 += k2; x1 += k0 + 2u;
    RD_(13) RD_(15) RD_(26) RD_(6)   x0 += k0; x1 += k1 + 3u;
    RD_(17) RD_(29) RD_(16) RD_(24)  x0 += k1; x1 += k2 + 4u;
    RD_(13) RD_(15) RD_(26) RD_(6)   x0 += k2; x1 += k0 + 5u;
#undef RD_
    o0 = x0; o1 = x1;
}

__device__ __forceinline__ float erfinv_fast(float x) {
    float w = -__logf(fmaf(-x, x, 1.0f));
    float p;
    if (w < 5.0f) {
        w = w - 2.5f;
        p =              2.81022636e-08f;
        p = fmaf(p, w,   3.43273939e-07f);
        p = fmaf(p, w,  -3.5233877e-06f);
        p = fmaf(p, w,  -4.39150654e-06f);
        p = fmaf(p, w,   0.00021858087f);
        p = fmaf(p, w,  -0.00125372503f);
        p = fmaf(p, w,  -0.00417768164f);
        p = fmaf(p, w,   0.246640727f);
        p = fmaf(p, w,   1.50140941f);
    } else {
        w = sqrtf(w) - 3.0f;
        p =             -0.000200214257f;
        p = fmaf(p, w,   0.000100950558f);
        p = fmaf(p, w,   0.00134934322f);
        p = fmaf(p, w,  -0.00367342844f);
        p = fmaf(p, w,   0.00573950773f);
        p = fmaf(p, w,  -0.0076224613f);
        p = fmaf(p, w,   0.00943887047f);
        p = fmaf(p, w,   1.00167406f);
        p = fmaf(p, w,   2.83297682f);
    }
    return p * x;
}

__device__ __forceinline__ float bits_to_noise(unsigned bits) {
    const float LO = -0.99999994039535522461f;
    float u01 = __uint_as_float((bits >> 9) | 0x3f800000u) - 1.0f;
    float val = fmaxf(LO, u01 * 2.0f + LO);
    return 1.41421356237f * erfinv_fast(val) * 0.01f;
}

// ---------- Precompute 1 (unchanged from R11) ----------
__global__ __launch_bounds__(512) void kpre1(
        const float* __restrict__ ts, const float* __restrict__ sts,
        const int* __restrict__ user, const float* __restrict__ upref,
        const float* __restrict__ wq_w, const float* __restrict__ wq_b,
        const float* __restrict__ wk_w, const float* __restrict__ wk_b,
        const float* __restrict__ wv_w, const float* __restrict__ wv_b) {
    __shared__ float redbuf[2048];
    int unit = blockIdx.x;
    int e = threadIdx.x & 63, part = threadIdx.x >> 6;
    int d0 = part * 32;
    if (blockIdx.x == 0 && threadIdx.x == 0) {
        unsigned a0, a1, b0, b1;
        tf2x32(0u, 42u, 0u, 0u, a0, a1);
        tf2x32(0u, 42u, 0u, 1u, b0, b1);
        d_ku[0] = a0; d_ku[1] = a1; d_kv[0] = b0; d_kv[1] = b1;
    }
    if (unit < 96) {
        float (*red)[8][64] = (float(*)[8][64])redbuf;
        int h = unit / 24, t = unit % 24;
        const float* xs = sts + t * D_ + d0;
        const float* xt = ts  + t * D_ + d0;
        const float* wk = wk_w + (h*D_ + d0)*HD_ + e;
        const float* wv = wv_w + (h*D_ + d0)*HD_ + e;
        const float* wq = wq_w + (h*2*D_ + D_ + d0)*HD_ + e;
        float k0=0,k1=0,k2=0,k3=0, v0=0,v1=0,v2=0,v3=0, q0=0,q1=0,q2=0,q3=0;
        #pragma unroll
        for (int d = 0; d < 32; d += 4) {
            float x0 = xs[d], x1 = xs[d+1], x2 = xs[d+2], x3 = xs[d+3];
            k0 = fmaf(x0, wk[(d  )*HD_], k0); k1 = fmaf(x1, wk[(d+1)*HD_], k1);
            k2 = fmaf(x2, wk[(d+2)*HD_], k2); k3 = fmaf(x3, wk[(d+3)*HD_], k3);
            v0 = fmaf(x0, wv[(d  )*HD_], v0); v1 = fmaf(x1, wv[(d+1)*HD_], v1);
            v2 = fmaf(x2, wv[(d+2)*HD_], v2); v3 = fmaf(x3, wv[(d+3)*HD_], v3);
            float y0 = xt[d], y1 = xt[d+1], y2 = xt[d+2], y3 = xt[d+3];
            q0 = fmaf(y0, wq[(d  )*HD_], q0); q1 = fmaf(y1, wq[(d+1)*HD_], q1);
            q2 = fmaf(y2, wq[(d+2)*HD_], q2); q3 = fmaf(y3, wq[(d+3)*HD_], q3);
        }
        red[0][part][e] = (k0 + k1) + (k2 + k3);
        red[1][part][e] = (v0 + v1) + (v2 + v3);
        red[2][part][e] = (q0 + q1) + (q2 + q3);
        __syncthreads();
        if (part < 3) {
            float s = ((red[part][0][e] + red[part][1][e])
                     + (red[part][2][e] + red[part][3][e]))
                    + ((red[part][4][e] + red[part][5][e])
                     + (red[part][6][e] + red[part][7][e]));
            if      (part == 0) d_k [unit*HD_ + e] = s + wk_b[h*HD_ + e];
            else if (part == 1) d_v [unit*HD_ + e] = s + wv_b[h*HD_ + e];
            else                d_qt[unit*HD_ + e] = s;
        }
    } else {
        float (*red)[64][4] = (float(*)[64][4])redbuf;
        int j = unit - 96;
        int h = j >> 5;
        int bg = (j & 31) * 4;
        const float* up0 = upref + (size_t)user[bg+0]*D_ + d0;
        const float* up1 = upref + (size_t)user[bg+1]*D_ + d0;
        const float* up2 = upref + (size_t)user[bg+2]*D_ + d0;
        const float* up3 = upref + (size_t)user[bg+3]*D_ + d0;
        const float* wq = wq_w + (h*2*D_ + d0)*HD_ + e;
        float a0=0, a1=0, a2=0, a3=0;
        #pragma unroll 8
        for (int d = 0; d < 32; d++) {
            float w = wq[d*HD_];
            a0 = fmaf(__ldg(up0 + d), w, a0);
            a1 = fmaf(__ldg(up1 + d), w, a1);
            a2 = fmaf(__ldg(up2 + d), w, a2);
            a3 = fmaf(__ldg(up3 + d), w, a3);
        }
        red[part][e][0] = a0; red[part][e][1] = a1;
        red[part][e][2] = a2; red[part][e][3] = a3;
        __syncthreads();
        if (part < 4) {
            float s = ((red[0][e][part] + red[1][e][part])
                     + (red[2][e][part] + red[3][e][part]))
                    + ((red[4][e][part] + red[5][e][part])
                     + (red[6][e][part] + red[7][e][part]));
            d_qu[(h*B_ + bg + part)*HD_ + e] = s + wq_b[h*HD_ + e];
        }
    }
}

// ---------- Precompute 2: W2 (paired), Wh, st, su, biases ----------
__global__ __launch_bounds__(256) void kpre2(
        const float* __restrict__ uw, const float* __restrict__ ub,
        const float* __restrict__ hw, const float* __restrict__ hb) {
    int bid = blockIdx.x, tid = threadIdx.x;
    if (bid < 96) {
        int h = bid / 24, t = bid % 24, kt = bid;
        {
            float a0 = 0, a1 = 0, a2 = 0, a3 = 0;
            const float* u = uw + h*HD_*D_ + tid;
            #pragma unroll 4
            for (int e = 0; e < HD_; e += 4) {
                a0 = fmaf(d_v[kt*HD_+e  ], u[(e  )*D_], a0);
                a1 = fmaf(d_v[kt*HD_+e+1], u[(e+1)*D_], a1);
                a2 = fmaf(d_v[kt*HD_+e+2], u[(e+2)*D_], a2);
                a3 = fmaf(d_v[kt*HD_+e+3], u[(e+3)*D_], a3);
            }
            float w = (a0 + a1) + (a2 + a3);
            // interleaved pair layout: W2[kp][c] = (W[2kp][c], W[2kp+1][c])
            ((float*)d_W2)[((((unsigned)kt >> 1)*256 + tid) << 1) | (kt & 1)] = w;
        }
        if (tid < 24) {
            float a0 = 0, a1 = 0;
            const float* hwp = hw + h*HD_*T_ + tid;
            #pragma unroll 4
            for (int e = 0; e < HD_; e += 2) {
                a0 = fmaf(d_v[kt*HD_+e  ], hwp[(e  )*T_], a0);
                a1 = fmaf(d_v[kt*HD_+e+1], hwp[(e+1)*T_], a1);
            }
            d_Wh[kt*24 + tid] = a0 + a1;
        }
        if (tid >= 32 && tid < 56) {
            int t2 = tid - 32;
            float a0 = 0, a1 = 0;
            #pragma unroll 4
            for (int e = 0; e < HD_; e += 2) {
                a0 = fmaf(d_qt[kt*HD_+e  ], d_k[(h*T_+t2)*HD_+e  ], a0);
                a1 = fmaf(d_qt[kt*HD_+e+1], d_k[(h*T_+t2)*HD_+e+1], a1);
            }
            d_st[(h*T_ + t)*T_ + t2] = (a0 + a1) * 0.125f;
        }
        if (bid == 0) d_bias[tid] = ub[tid];
        if (bid == 1 && tid < 24) d_bias[256 + tid] = hb[tid];
    } else {
        int j = (bid - 96) * 256 + tid;
        int hb2 = j / 24, t = j % 24;
        int h = hb2 >> 7;
        float a0 = 0, a1 = 0, a2 = 0, a3 = 0;
        #pragma unroll 4
        for (int e = 0; e < HD_; e += 4) {
            a0 = fmaf(d_qu[hb2*HD_+e  ], d_k[(h*T_+t)*HD_+e  ], a0);
            a1 = fmaf(d_qu[hb2*HD_+e+1], d_k[(h*T_+t)*HD_+e+1], a1);
            a2 = fmaf(d_qu[hb2*HD_+e+2], d_k[(h*T_+t)*HD_+e+2], a2);
            a3 = fmaf(d_qu[hb2*HD_+e+3], d_k[(h*T_+t)*HD_+e+3], a3);
        }
        d_su[hb2*T_ + t] = ((a0 + a1) + (a2 + a3)) * 0.125f;
    }
}

// ---------- kscore: scores + noise + softmax + head logits; probs -> d_P ----
#define TR_    128
#define ZS_    98
#define SHZ_B  (TR_*ZS_*4)                 // 50176
#define QU_B   SHZ_B                       // queue after shZ
#define WH_B   (QU_B + 24576)              // head-W after queue: 74752
#define KSC_SMEM (WH_B + 96*12*8)          // 83968

__global__ __launch_bounds__(512, 2) void kscore(const int* __restrict__ hour,
                                                 const int* __restrict__ mask,
                                                 float* __restrict__ out) {
    extern __shared__ char smembuf[];
    float* shZ  = (float*)smembuf;
    ushortx* queue = (ushortx*)(smembuf + QU_B);
    ull*   shWh = (ull*)(smembuf + WH_B);
    __shared__ int cnt;

    int tid = threadIdx.x;
    int lane = tid & 31;
    int tile0 = blockIdx.x * TR_;
    if (tid == 0) cnt = 0;
    for (int i = tid; i < 96*12; i += 512) {
        int kk = i / 12, c = i - kk*12;
        shWh[i] = *(const ull*)(d_Wh + kk*24 + 2*c);
    }
    __syncthreads();

    unsigned ku0 = d_ku[0], ku1 = d_ku[1];
    unsigned kv0 = d_kv[0], kv1 = d_kv[1];

    // ---- A1: z = relu(I); need test on I^2; warp-scan compaction ----
    {
        int r = tid >> 2, h = tid & 3;
        int n = tile0 + r;
        int b = n >> 9;
        int tau = hour[n];
        const int4*   mp  = (const int4*)(mask + n*24);
        const float4* sup = (const float4*)(d_su + (h*B_ + b)*T_);
        const float4* stp = (const float4*)(d_st + (h*T_ + tau)*T_);
        float* zrow = shZ + r*ZS_ + h*24;
        unsigned needmask = 0u;
        #pragma unroll
        for (int j = 0; j < 6; j++) {
            int4 m4 = __ldg(mp + j);
            float4 s4 = sup[j];
            float4 t4 = stp[j];
            int   mv[4] = {m4.x, m4.y, m4.z, m4.w};
            float sv[4] = {s4.x, s4.y, s4.z, s4.w};
            float tv[4] = {t4.x, t4.y, t4.z, t4.w};
            #pragma unroll
            for (int q = 0; q < 4; q++) {
                int t = j*4 + q;
                float z = 0.0f;
                if (!mv[q]) {
                    float I = sv[q] + tv[q];
                    z = fmaxf(I, 0.0f);
                    if (I*I < NOISE_TH) needmask |= (1u << t);
                }
                zrow[t] = z;
            }
        }
        int cc = __popc(needmask);
        int pre = cc;
        #pragma unroll
        for (int off = 1; off < 32; off <<= 1) {
            int v = __shfl_up_sync(0xffffffffu, pre, off);
            if (lane >= off) pre += v;
        }
        int wtotal = __shfl_sync(0xffffffffu, pre, 31);
        int base = 0;
        if (lane == 31 && wtotal) base = atomicAdd(&cnt, wtotal);
        base = __shfl_sync(0xffffffffu, base, 31);
        int wpos = base + pre - cc;
        unsigned m = needmask;
        while (m) {
            int t = __ffs(m) - 1;
            m &= m - 1u;
            queue[wpos++] = (ushortx)(tid*24 + t);
        }
    }
    __syncthreads();

    // ---- A2: dense threefry over queued slots ----
    {
        int total = cnt;
        for (int i = tid; i < total; i += 512) {
            int sid = queue[i];
            int t = sid % 24;
            int rh = sid / 24;
            int r = rh >> 2, h = rh & 3;
            int n = tile0 + r;
            int b = n >> 9;
            int tau = hour[n];
            float I = d_su[(h*B_ + b)*T_ + t] + d_st[(h*T_ + tau)*T_ + t];
            float g = __expf((KOSC * I) * I);
            unsigned idx = (unsigned)(n*24 + t) + (unsigned)h * (unsigned)NT_;
            unsigned a0, a1, c0, c1;
            tf2x32(ku0, ku1, 0u, idx, a0, a1);
            tf2x32(kv0, kv1, 0u, idx, c0, c1);
            float dn = bits_to_noise(a0 ^ a1) - bits_to_noise(c0 ^ c1);
            shZ[r*ZS_ + h*24 + t] += dn * g;
        }
    }
    __syncthreads();

    // ---- softmax in regs; write probs in place + stream to d_P ----
    {
        int r = tid >> 2, h = tid & 3;
        float* zrow = shZ + r*ZS_ + h*24;
        float pp[24];
        #pragma unroll
        for (int t = 0; t < 24; t++) pp[t] = zrow[t];
        float mx = pp[0];
        #pragma unroll
        for (int t = 1; t < 24; t++) mx = fmaxf(mx, pp[t]);
        float s = 0.0f;
        #pragma unroll
        for (int t = 0; t < 24; t++) { pp[t] = __expf(pp[t] - mx); s += pp[t]; }
        float inv = __fdividef(1.0f, s);
        #pragma unroll
        for (int t = 0; t < 24; t++) pp[t] *= inv;
        #pragma unroll
        for (int t = 0; t < 24; t++) zrow[t] = pp[t];
        // stream to global for kgemm
        int n = tile0 + r;
        float4* dst = (float4*)(d_P + (size_t)n*96 + h*24);
        #pragma unroll
        for (int j = 0; j < 6; j++)
            dst[j] = make_float4(pp[4*j], pp[4*j+1], pp[4*j+2], pp[4*j+3]);
    }
    __syncthreads();

    // ---- head phase: 24 logit cols ----
    {
        int r = tid >> 2, q = tid & 3;
        const float* prow = shZ + r*ZS_;
        ull a0 = 0ull, a1 = 0ull, a2 = 0ull;
        #pragma unroll 4
        for (int kk = 0; kk < 96; kk++) {
            ull p2 = dup2(prow[kk]);
            ffma2(a0, p2, shWh[kk*12 + q*3 + 0]);
            ffma2(a1, p2, shWh[kk*12 + q*3 + 1]);
            ffma2(a2, p2, shWh[kk*12 + q*3 + 2]);
        }
        int n = tile0 + r;
        float* outlg = out + (size_t)N_ * D_ + (size_t)n * T_;
        int cp = q*3;
        float2 f0 = *(float2*)&a0, f1 = *(float2*)&a1, f2 = *(float2*)&a2;
        f0.x += d_bias[256 + 2*cp + 0]; f0.y += d_bias[256 + 2*cp + 1];
        f1.x += d_bias[256 + 2*cp + 2]; f1.y += d_bias[256 + 2*cp + 3];
        f2.x += d_bias[256 + 2*cp + 4]; f2.y += d_bias[256 + 2*cp + 5];
        *(float2*)(outlg + 2*cp + 0) = f0;
        *(float2*)(outlg + 2*cp + 2) = f1;
        *(float2*)(outlg + 2*cp + 4) = f2;
    }
}

// ---------- kgemm: out[128,256] = P[128,96] @ W[96,256] + bias ----------
// k-pair packed FFMA2: acc.x sums even k, acc.y sums odd k; no dup movs.
// W2S_ = 256 (EVEN): rows 16B-aligned for the float4 copy; inner loop reads
// are same-row consecutive-lane LDS.64 -> conflict-free without padding.
#define W2S_  256                          // ull stride of W2 smem rows
#define KG_PROBS_B (TR_*96*4)              // 49152
#define KG_SMEM (KG_PROBS_B + 48*W2S_*8)   // 49152 + 98304 = 147456

__global__ __launch_bounds__(512) void kgemm(float* __restrict__ out) {
    extern __shared__ char sm[];
    float* shP = (float*)sm;                       // [128][96]
    ull*   shW = (ull*)(sm + KG_PROBS_B);          // [48][256]
    int tid = threadIdx.x;
    int tile0 = blockIdx.x * TR_;

    {   // probs: 128 rows x 96 floats = 3072 float4
        const float4* src = (const float4*)(d_P + (size_t)tile0*96);
        float4* dst = (float4*)shP;
        for (int i = tid; i < 3072; i += 512) dst[i] = src[i];
    }
    {   // W2: 48 x 256 ull = 6144 float4, contiguous (stride == row length)
        const float4* src = (const float4*)d_W2;
        float4* dst = (float4*)shW;
        for (int i = tid; i < 6144; i += 512) dst[i] = src[i];
    }
    __syncthreads();

    #pragma unroll
    for (int pass = 0; pass < 2; pass++) {
        int unit = tid + pass*512;
        int rg = unit >> 5, cs = unit & 31;    // 32 rowgroups x 32 colsets
        int r0 = rg * 4;
        ull acc[4][8];
        #pragma unroll
        for (int i = 0; i < 4; i++)
            #pragma unroll
            for (int j = 0; j < 8; j++) acc[i][j] = 0ull;
        const float* pbase = shP + r0*96;
        const ull*   wbase = shW + cs;
        #pragma unroll 4
        for (int kp = 0; kp < 48; kp++) {
            ull w0 = wbase[kp*W2S_ +   0];
            ull w1 = wbase[kp*W2S_ +  32];
            ull w2 = wbase[kp*W2S_ +  64];
            ull w3 = wbase[kp*W2S_ +  96];
            ull w4 = wbase[kp*W2S_ + 128];
            ull w5 = wbase[kp*W2S_ + 160];
            ull w6 = wbase[kp*W2S_ + 192];
            ull w7 = wbase[kp*W2S_ + 224];
            #pragma unroll
            for (int i = 0; i < 4; i++) {
                ull pr = *(const ull*)(pbase + i*96 + 2*kp);
                ffma2(acc[i][0], pr, w0);
                ffma2(acc[i][1], pr, w1);
                ffma2(acc[i][2], pr, w2);
                ffma2(acc[i][3], pr, w3);
                ffma2(acc[i][4], pr, w4);
                ffma2(acc[i][5], pr, w5);
                ffma2(acc[i][6], pr, w6);
                ffma2(acc[i][7], pr, w7);
            }
        }
        float bj[8];
        #pragma unroll
        for (int j = 0; j < 8; j++) bj[j] = __ldg(d_bias + cs + 32*j);
        #pragma unroll
        for (int i = 0; i < 4; i++) {
            float* orow = out + (size_t)(tile0 + r0 + i)*D_ + cs;
            #pragma unroll
            for (int j = 0; j < 8; j++) {
                float2 f = *(float2*)&acc[i][j];
                orow[32*j] = (f.x + f.y) + bj[j];
            }
        }
    }
}

extern "C" void kernel_launch(void* const* d_in, const int* in_sizes, int n_in,
                              void* d_out, int out_size) {
    const float* ts    = (const float*)d_in[0];
    const float* sts   = (const float*)d_in[1];
    const int*   user  = (const int*)d_in[3];
    const int*   hour  = (const int*)d_in[4];
    const int*   mask  = (const int*)d_in[5];
    const float* upref = (const float*)d_in[6];
    const float* wq_w  = (const float*)d_in[7];
    const float* wq_b  = (const float*)d_in[8];
    const float* wk_w  = (const float*)d_in[9];
    const float* wk_b  = (const float*)d_in[10];
    const float* wv_w  = (const float*)d_in[11];
    const float* wv_b  = (const float*)d_in[12];
    const float* uw    = (const float*)d_in[13];
    const float* ub    = (const float*)d_in[14];
    const float* hw    = (const float*)d_in[15];
    const float* hb    = (const float*)d_in[16];
    float* out = (float*)d_out;

    cudaFuncSetAttribute(kscore, cudaFuncAttributeMaxDynamicSharedMemorySize,
                         (int)KSC_SMEM);
    cudaFuncSetAttribute(kgemm, cudaFuncAttributeMaxDynamicSharedMemorySize,
                         (int)KG_SMEM);

    kpre1<<<224, 512>>>(ts, sts, user, upref, wq_w, wq_b, wk_w, wk_b, wv_w, wv_b);
    kpre2<<<144, 256>>>(uw, ub, hw, hb);
    kscore<<<N_ / TR_, 512, KSC_SMEM>>>(hour, mask, out);
    kgemm<<<N_ / TR_, 512, KG_SMEM>>>(out);
}